// round 1
// baseline (speedup 1.0000x reference)
#include <cuda_runtime.h>
#include <cstdint>
#include <cstdio>

// Problem constants
#define TT   256
#define NN   1024
#define HH   256
#define LLN  16
#define NLN  32
#define CCN  64
#define NAN_ 16
#define OUTW 278   // 4 + 256 + 16 + 2

// ---------------- scratch (device globals; no allocations allowed) ----------------
__device__ float S_MFLAT[16384 * 256];          // embed[lines] rows n*L+l
__device__ float S_GF[16384 * 768];             // forward  gi per distinct (n,l)
__device__ float S_GB[16384 * 768];             // backward gi per distinct (n,l)
__device__ float S_E0[16384 * 256];             // encoder ping-pong fwd
__device__ float S_E1[16384 * 256];
__device__ float S_E2[16384 * 256];             // encoder ping-pong bwd
__device__ float S_E3[16384 * 256];
__device__ float S_HCAT[16384 * 512];           // concat(hf, hb) rows l*N+n
__device__ float S_RP[16384 * 256];             // f_w0[:,C:] @ Hmem
__device__ float S_B1[262144 * 256];            // Acond, later reused as X3
__device__ float S_X1[262144 * 256];
__device__ float S_X2[262144 * 256];
__device__ float S_GI[(size_t)262144 * 768];    // main-loop gi for all t
__device__ float S_H0[1024 * 256];              // main-loop h ping-pong
__device__ float S_H1[1024 * 256];

__device__ __forceinline__ float sigm(float x) { return 1.0f / (1.0f + expf(-x)); }

// ---------------- generic tiled SGEMM: C = op(A @ W^T + bias) ----------------
// A: [M,K] row-major (lda), W: [Nc, *] row-major (ldw), element W[row*ldw + wcol0 + k]
// C: [M,Nc] (ldc). Requires M%64==0, Nc%64==0, K%16==0.
__global__ __launch_bounds__(256) void gemm_kernel(
    const float* __restrict__ A, int lda,
    const float* __restrict__ W, int ldw, int wcol0,
    const float* __restrict__ bias,
    float* __restrict__ C, int ldc,
    int K, int relu)
{
    __shared__ float As[16][64];
    __shared__ float Ws[16][64];
    const int bm = blockIdx.x * 64;
    const int bn = blockIdx.y * 64;
    const int tid = threadIdx.x;
    const int tx = tid & 15, ty = tid >> 4;
    const int lm = tid & 63;
    const int lk = (tid >> 6) << 2;

    float acc[4][4] = {};

    const float* Aptr = A + (size_t)(bm + lm) * lda + lk;
    const float* Wptr = W + (size_t)(bn + lm) * ldw + wcol0 + lk;

    for (int k0 = 0; k0 < K; k0 += 16) {
        float4 av = *reinterpret_cast<const float4*>(Aptr + k0);
        float4 wv = *reinterpret_cast<const float4*>(Wptr + k0);
        As[lk + 0][lm] = av.x; As[lk + 1][lm] = av.y;
        As[lk + 2][lm] = av.z; As[lk + 3][lm] = av.w;
        Ws[lk + 0][lm] = wv.x; Ws[lk + 1][lm] = wv.y;
        Ws[lk + 2][lm] = wv.z; Ws[lk + 3][lm] = wv.w;
        __syncthreads();
#pragma unroll
        for (int k = 0; k < 16; k++) {
            float4 a4 = *reinterpret_cast<const float4*>(&As[k][ty << 2]);
            float4 b4 = *reinterpret_cast<const float4*>(&Ws[k][tx << 2]);
            float a[4] = {a4.x, a4.y, a4.z, a4.w};
            float b[4] = {b4.x, b4.y, b4.z, b4.w};
#pragma unroll
            for (int i = 0; i < 4; i++)
#pragma unroll
                for (int j = 0; j < 4; j++)
                    acc[i][j] += a[i] * b[j];
        }
        __syncthreads();
    }

#pragma unroll
    for (int i = 0; i < 4; i++) {
        int row = bm + (ty << 2) + i;
        int col0 = bn + (tx << 2);
        float4 v;
        float vv[4];
#pragma unroll
        for (int j = 0; j < 4; j++) {
            float x = acc[i][j];
            if (bias) x += bias[col0 + j];
            if (relu) x = fmaxf(x, 0.0f);
            vv[j] = x;
        }
        v.x = vv[0]; v.y = vv[1]; v.z = vv[2]; v.w = vv[3];
        *reinterpret_cast<float4*>(&C[(size_t)row * ldc + col0]) = v;
    }
}

// ---------------- fused GRU step: gh GEMM (3 gates) + gate update ----------------
// Hin [B,256] (ignored when hzero), Whh [768,256], gi precomputed (incl bih).
// mode 0 (encoder): gi row = n*16 + ((roll + tparam) & 15), b = roll*1024 + n.
// mode 1 (main):    gi row = tparam*1024 + b; also writes h into out[t,n,4+j].
__global__ __launch_bounds__(256) void gru_step_kernel(
    const float* __restrict__ Hin,
    const float* __restrict__ Whh,
    const float* __restrict__ bhh,
    const float* __restrict__ GI,
    float* __restrict__ Hout,
    float* __restrict__ outp,
    int hzero, int mode, int tparam)
{
    __shared__ float As[16][64];
    __shared__ float Ws[3][16][64];
    const int bm = blockIdx.x * 64;
    const int bn = blockIdx.y * 64;          // 0..192 (within H=256)
    const int tid = threadIdx.x;
    const int tx = tid & 15, ty = tid >> 4;
    const int lm = tid & 63;
    const int lk = (tid >> 6) << 2;

    float aR[4][4] = {}, aZ[4][4] = {}, aN[4][4] = {};

    if (!hzero) {
        const float* Aptr = Hin + (size_t)(bm + lm) * 256 + lk;
        for (int k0 = 0; k0 < 256; k0 += 16) {
            float4 av = *reinterpret_cast<const float4*>(Aptr + k0);
            As[lk + 0][lm] = av.x; As[lk + 1][lm] = av.y;
            As[lk + 2][lm] = av.z; As[lk + 3][lm] = av.w;
#pragma unroll
            for (int g = 0; g < 3; g++) {
                float4 wv = *reinterpret_cast<const float4*>(
                    Whh + (size_t)(g * 256 + bn + lm) * 256 + k0 + lk);
                Ws[g][lk + 0][lm] = wv.x; Ws[g][lk + 1][lm] = wv.y;
                Ws[g][lk + 2][lm] = wv.z; Ws[g][lk + 3][lm] = wv.w;
            }
            __syncthreads();
#pragma unroll
            for (int k = 0; k < 16; k++) {
                float4 a4 = *reinterpret_cast<const float4*>(&As[k][ty << 2]);
                float4 r4 = *reinterpret_cast<const float4*>(&Ws[0][k][tx << 2]);
                float4 z4 = *reinterpret_cast<const float4*>(&Ws[1][k][tx << 2]);
                float4 n4 = *reinterpret_cast<const float4*>(&Ws[2][k][tx << 2]);
                float a[4]  = {a4.x, a4.y, a4.z, a4.w};
                float br[4] = {r4.x, r4.y, r4.z, r4.w};
                float bz[4] = {z4.x, z4.y, z4.z, z4.w};
                float bn_[4] = {n4.x, n4.y, n4.z, n4.w};
#pragma unroll
                for (int i = 0; i < 4; i++)
#pragma unroll
                    for (int j = 0; j < 4; j++) {
                        aR[i][j] += a[i] * br[j];
                        aZ[i][j] += a[i] * bz[j];
                        aN[i][j] += a[i] * bn_[j];
                    }
            }
            __syncthreads();
        }
    }

    const int col0 = bn + (tx << 2);
    float bh_r[4], bh_z[4], bh_n[4];
#pragma unroll
    for (int j = 0; j < 4; j++) {
        bh_r[j] = bhh[col0 + j];
        bh_z[j] = bhh[256 + col0 + j];
        bh_n[j] = bhh[512 + col0 + j];
    }

#pragma unroll
    for (int i = 0; i < 4; i++) {
        int row = bm + (ty << 2) + i;
        size_t girow;
        if (mode == 0) {
            int n = row & 1023;
            int roll = row >> 10;
            int l = (roll + tparam) & 15;
            girow = (size_t)n * 16 + l;
        } else {
            girow = (size_t)tparam * 1024 + row;
        }
        const float* gi = GI + girow * 768 + col0;
        float4 gr4 = *reinterpret_cast<const float4*>(gi);
        float4 gz4 = *reinterpret_cast<const float4*>(gi + 256);
        float4 gn4 = *reinterpret_cast<const float4*>(gi + 512);
        float4 ho4 = make_float4(0.f, 0.f, 0.f, 0.f);
        if (!hzero)
            ho4 = *reinterpret_cast<const float4*>(Hin + (size_t)row * 256 + col0);
        float gr[4] = {gr4.x, gr4.y, gr4.z, gr4.w};
        float gz[4] = {gz4.x, gz4.y, gz4.z, gz4.w};
        float gn[4] = {gn4.x, gn4.y, gn4.z, gn4.w};
        float ho[4] = {ho4.x, ho4.y, ho4.z, ho4.w};
        float hv[4];
#pragma unroll
        for (int j = 0; j < 4; j++) {
            float r = sigm(gr[j] + aR[i][j] + bh_r[j]);
            float z = sigm(gz[j] + aZ[i][j] + bh_z[j]);
            float nn = tanhf(gn[j] + r * (aN[i][j] + bh_n[j]));
            hv[j] = (1.0f - z) * nn + z * ho[j];
        }
        float4 hq; hq.x = hv[0]; hq.y = hv[1]; hq.z = hv[2]; hq.w = hv[3];
        *reinterpret_cast<float4*>(Hout + (size_t)row * 256 + col0) = hq;
        if (outp) {
            float* orow = outp + ((size_t)tparam * 1024 + row) * OUTW + 4 + col0;
            orow[0] = hv[0]; orow[1] = hv[1]; orow[2] = hv[2]; orow[3] = hv[3];
        }
    }
}

// ---------------- misc small kernels ----------------
__global__ void gather_kernel(const int* __restrict__ lines,
                              const float* __restrict__ embed)
{
    int i = blockIdx.x;                      // 0..16383 = n*L + l
    int line = lines[i];
    S_MFLAT[(size_t)i * 256 + threadIdx.x] = embed[(size_t)line * 256 + threadIdx.x];
}

__global__ void hcat_kernel()
{
    int i = blockIdx.x;                      // 0..16383 = l*N + n (roll-major)
    int t = threadIdx.x;
    S_HCAT[(size_t)i * 512 + t]       = S_E0[(size_t)i * 256 + t];  // hf final
    S_HCAT[(size_t)i * 512 + 256 + t] = S_E2[(size_t)i * 256 + t];  // hb final
}

__global__ void x1_kernel(const int* __restrict__ active,
                          const float* __restrict__ b0)
{
    size_t i = blockIdx.x;                   // 0..262143 = t*N + n
    int n = (int)(i & 1023);
    int w = active[i];
    int h = threadIdx.x;
    float v = S_B1[i * 256 + h] + S_RP[((size_t)w * 1024 + n) * 256 + h] + b0[h];
    S_X1[i * 256 + h] = fmaxf(v, 0.0f);
}

// actor/critic/softmax + packing of a/p/w/pp, reading h back from out
__global__ __launch_bounds__(256) void head_kernel(
    float* __restrict__ out,
    const float* __restrict__ w_actor, const float* __restrict__ b_actor,
    const float* __restrict__ w_critic, const float* __restrict__ b_critic,
    const int* __restrict__ actions, const int* __restrict__ active,
    const float* __restrict__ p0, const float* __restrict__ pp0)
{
    __shared__ float wa[16][257];
    __shared__ float wc[256];
    int tid = threadIdx.x;
    for (int idx = tid; idx < 16 * 256; idx += 256)
        wa[idx >> 8][idx & 255] = w_actor[idx];
    wc[tid] = w_critic[tid];
    __syncthreads();

    int warp = tid >> 5, lane = tid & 31;
#pragma unroll 1
    for (int rr = 0; rr < 4; rr++) {
        size_t row = (size_t)blockIdx.x * 32 + warp * 4 + rr;   // 0..262143
        float* orow = out + row * OUTW;
        const float* hrow = orow + 4;
        const float* wrow = (lane < 16) ? wa[lane] : wc;
        float acc = 0.0f;
#pragma unroll 8
        for (int j = 0; j < 256; j++) acc += hrow[j] * wrow[j];
        if (lane < 16) acc += b_actor[lane];
        else if (lane == 16) acc += b_critic[0];

        // softmax among lanes 0..15
        float lg = (lane < 16) ? acc : -1e30f;
        float m = lg;
#pragma unroll
        for (int o = 8; o > 0; o >>= 1)
            m = fmaxf(m, __shfl_xor_sync(0xffffffffu, m, o, 16));
        float e = expf(lg - m);
        float s = e;
#pragma unroll
        for (int o = 8; o > 0; o >>= 1)
            s += __shfl_xor_sync(0xffffffffu, s, o, 16);
        float p = e / s;

        int n = (int)(row & 1023);
        if (lane < 16)       orow[260 + lane] = p;
        else if (lane == 16) orow[3]   = acc;
        else if (lane == 17) orow[0]   = (float)actions[row];
        else if (lane == 18) orow[1]   = p0[n];
        else if (lane == 19) orow[2]   = (float)active[row];
        else if (lane == 20) orow[276] = pp0[2 * n];
        else if (lane == 21) orow[277] = pp0[2 * n + 1];
    }
}

// ---------------- launcher ----------------
extern "C" void kernel_launch(void* const* d_in, const int* in_sizes, int n_in,
                              void* d_out, int out_size)
{
    const float* condition = (const float*)d_in[0];
    const int*   active    = (const int*)d_in[1];
    const int*   lines     = (const int*)d_in[2];
    const int*   actions   = (const int*)d_in[3];
    const float* h0        = (const float*)d_in[4];
    const float* p0        = (const float*)d_in[5];
    const float* pp0       = (const float*)d_in[6];
    const float* embed     = (const float*)d_in[7];
    const float* wih_f     = (const float*)d_in[8];
    const float* whh_f     = (const float*)d_in[9];
    const float* bih_f     = (const float*)d_in[10];
    const float* bhh_f     = (const float*)d_in[11];
    const float* wih_b     = (const float*)d_in[12];
    const float* whh_b     = (const float*)d_in[13];
    const float* bih_b     = (const float*)d_in[14];
    const float* bhh_b     = (const float*)d_in[15];
    const float* f_w0      = (const float*)d_in[16];
    const float* f_b0      = (const float*)d_in[17];
    const float* f_w1      = (const float*)d_in[18];
    const float* f_b1      = (const float*)d_in[19];
    const float* f_w2      = (const float*)d_in[20];
    const float* f_b2      = (const float*)d_in[21];
    const float* c_wih     = (const float*)d_in[22];
    const float* c_whh     = (const float*)d_in[23];
    const float* c_bih     = (const float*)d_in[24];
    const float* c_bhh     = (const float*)d_in[25];
    const float* w_critic  = (const float*)d_in[26];
    const float* b_critic  = (const float*)d_in[27];
    const float* w_actor   = (const float*)d_in[28];
    const float* b_actor   = (const float*)d_in[29];
    float* out = (float*)d_out;

    float *mflat, *gf, *gb, *e0, *e1, *e2, *e3, *hcat, *rp, *b1, *x1, *x2, *gi, *hh0, *hh1;
    cudaGetSymbolAddress((void**)&mflat, S_MFLAT);
    cudaGetSymbolAddress((void**)&gf,    S_GF);
    cudaGetSymbolAddress((void**)&gb,    S_GB);
    cudaGetSymbolAddress((void**)&e0,    S_E0);
    cudaGetSymbolAddress((void**)&e1,    S_E1);
    cudaGetSymbolAddress((void**)&e2,    S_E2);
    cudaGetSymbolAddress((void**)&e3,    S_E3);
    cudaGetSymbolAddress((void**)&hcat,  S_HCAT);
    cudaGetSymbolAddress((void**)&rp,    S_RP);
    cudaGetSymbolAddress((void**)&b1,    S_B1);
    cudaGetSymbolAddress((void**)&x1,    S_X1);
    cudaGetSymbolAddress((void**)&x2,    S_X2);
    cudaGetSymbolAddress((void**)&gi,    S_GI);
    cudaGetSymbolAddress((void**)&hh0,   S_H0);
    cudaGetSymbolAddress((void**)&hh1,   S_H1);

    // ---- task encoder ----
    gather_kernel<<<16384, 256>>>(lines, embed);

    // gi precompute over the 16384 distinct (n,l) rows (includes bih)
    gemm_kernel<<<dim3(256, 12), 256>>>(mflat, 256, wih_f, 256, 0, bih_f, gf, 768, 256, 0);
    gemm_kernel<<<dim3(256, 12), 256>>>(mflat, 256, wih_b, 256, 0, bih_b, gb, 768, 256, 0);

    // forward scan over 16 steps (batch = 16 rolls x 1024)
    for (int t = 0; t < 16; t++) {
        const float* src = (t & 1) ? e1 : e0;
        float* dst = (t & 1) ? e0 : e1;        // t=15 (odd) -> e0 final
        gru_step_kernel<<<dim3(256, 4), 256>>>(src, whh_f, bhh_f, gf, dst, nullptr,
                                               t == 0, 0, t);
    }
    // backward scan
    for (int s = 0; s < 16; s++) {
        const float* src = (s & 1) ? e3 : e2;
        float* dst = (s & 1) ? e2 : e3;        // s=15 -> e2 final
        gru_step_kernel<<<dim3(256, 4), 256>>>(src, whh_b, bhh_b, gb, dst, nullptr,
                                               s == 0, 0, 15 - s);
    }
    hcat_kernel<<<16384, 256>>>();

    // ---- main-loop parallel precompute ----
    // Rp[l*N+n] = Hmem @ f_w0[:, C:].T
    gemm_kernel<<<dim3(256, 4), 256>>>(hcat, 512, f_w0, 576, 64, nullptr, rp, 256, 512, 0);
    // Acond[t*N+n] = cond @ f_w0[:, :C].T   (into b1)
    gemm_kernel<<<dim3(4096, 4), 256>>>(condition, 64, f_w0, 576, 0, nullptr, b1, 256, 64, 0);
    // x1 = relu(Acond + gather(Rp) + b0)
    x1_kernel<<<262144, 256>>>(active, f_b0);
    // x2 = relu(x1 @ f_w1.T + b1)
    gemm_kernel<<<dim3(4096, 4), 256>>>(x1, 256, f_w1, 256, 0, f_b1, x2, 256, 256, 1);
    // x3 = relu(x2 @ f_w2.T + b2) -> reuse b1
    gemm_kernel<<<dim3(4096, 4), 256>>>(x2, 256, f_w2, 256, 0, f_b2, b1, 256, 256, 1);
    // GI = x3 @ c_wih.T + c_bih
    gemm_kernel<<<dim3(4096, 12), 256>>>(b1, 256, c_wih, 256, 0, c_bih, gi, 768, 256, 0);

    // ---- sequential main loop: fused gh GEMM + gate update + h store ----
    for (int t = 0; t < 256; t++) {
        const float* src = (t == 0) ? h0 : ((t & 1) ? hh0 : hh1);
        float* dst = (t & 1) ? hh1 : hh0;
        gru_step_kernel<<<dim3(16, 4), 256>>>(src, c_whh, c_bhh, gi, dst, out,
                                              0, 1, t);
    }

    // ---- heads + packing (parallel over all T*N) ----
    head_kernel<<<8192, 256>>>(out, w_actor, b_actor, w_critic, b_critic,
                               actions, active, p0, pp0);
}

// round 2
// speedup vs baseline: 1.6386x; 1.6386x over previous
#include <cuda_runtime.h>
#include <cstdint>
#include <cstdio>

// Problem constants
#define TT   256
#define NN   1024
#define HH   256
#define LLN  16
#define NLN  32
#define CCN  64
#define OUTW 278   // 4 + 256 + 16 + 2

// ---------------- scratch (device globals; no allocations allowed) ----------------
__device__ float S_MFLAT[16384 * 256];          // embed[lines] rows n*L+l
__device__ float S_GF[16384 * 768];             // forward  gi per distinct (n,l)
__device__ float S_GB[16384 * 768];             // backward gi per distinct (n,l)
__device__ float S_GH[16384 * 768];             // encoder gh scratch
__device__ float S_GHM[1024 * 768];             // main-loop gh scratch
__device__ float S_E0[16384 * 256];             // encoder ping-pong fwd
__device__ float S_E1[16384 * 256];
__device__ float S_E2[16384 * 256];             // encoder ping-pong bwd
__device__ float S_E3[16384 * 256];
__device__ float S_HCAT[16384 * 512];           // concat(hf, hb) rows l*N+n
__device__ float S_RP[16384 * 256];             // f_w0[:,C:] @ Hmem
__device__ float S_B1[262144 * 256];            // Acond, later reused as X3
__device__ float S_X1[262144 * 256];
__device__ float S_X2[262144 * 256];
__device__ float S_GI[(size_t)262144 * 768];    // main-loop gi for all t
__device__ float S_H0[1024 * 256];              // main-loop h ping-pong
__device__ float S_H1[1024 * 256];

__device__ __forceinline__ float sigm(float x) { return 1.0f / (1.0f + expf(-x)); }

__device__ __forceinline__ unsigned f2tf(float x) {
    unsigned r;
    asm("cvt.rna.tf32.f32 %0, %1;" : "=r"(r) : "f"(x));
    return r;
}

// ---------------- tf32 tensor-core GEMM: C = op(A @ W^T + bias) ----------------
// A: [M,K] row-major (lda); W rows at W[row*ldw + wcol0 + k]; C: [M,Nc] (ldc).
// Tile 128x64, BK=16, 8 warps (4x2). Requires M%128==0, Nc%64==0, K%16==0.
__global__ __launch_bounds__(256) void mma_gemm_kernel(
    const float* __restrict__ A, int lda,
    const float* __restrict__ W, int ldw, int wcol0,
    const float* __restrict__ bias,
    float* __restrict__ C, int ldc,
    int K, int relu)
{
    __shared__ unsigned As[128][20];   // pad 20 -> conflict-free fragment loads
    __shared__ unsigned Bs[64][20];
    const int tid  = threadIdx.x;
    const int bm   = blockIdx.x * 128;
    const int bn   = blockIdx.y * 64;
    const int lane = tid & 31;
    const int warp = tid >> 5;
    const int wm   = (warp & 3) * 32;
    const int wn   = (warp >> 2) * 32;

    const int lr = tid >> 2;          // 0..63
    const int lk = (tid & 3) * 4;     // 0,4,8,12

    float acc[2][4][4];
#pragma unroll
    for (int a = 0; a < 2; a++)
#pragma unroll
        for (int b = 0; b < 4; b++)
#pragma unroll
            for (int c = 0; c < 4; c++) acc[a][b][c] = 0.0f;

    const float* Aptr0 = A + (size_t)(bm + lr) * lda + lk;
    const float* Aptr1 = A + (size_t)(bm + 64 + lr) * lda + lk;
    const float* Wptr  = W + (size_t)(bn + lr) * ldw + wcol0 + lk;

    for (int k0 = 0; k0 < K; k0 += 16) {
        float4 a0 = *reinterpret_cast<const float4*>(Aptr0 + k0);
        float4 a1 = *reinterpret_cast<const float4*>(Aptr1 + k0);
        float4 w0 = *reinterpret_cast<const float4*>(Wptr + k0);
        *reinterpret_cast<uint4*>(&As[lr][lk]) =
            make_uint4(f2tf(a0.x), f2tf(a0.y), f2tf(a0.z), f2tf(a0.w));
        *reinterpret_cast<uint4*>(&As[64 + lr][lk]) =
            make_uint4(f2tf(a1.x), f2tf(a1.y), f2tf(a1.z), f2tf(a1.w));
        *reinterpret_cast<uint4*>(&Bs[lr][lk]) =
            make_uint4(f2tf(w0.x), f2tf(w0.y), f2tf(w0.z), f2tf(w0.w));
        __syncthreads();
#pragma unroll
        for (int ks = 0; ks < 16; ks += 8) {
            unsigned af[2][4];
            unsigned bf[4][2];
#pragma unroll
            for (int mf = 0; mf < 2; mf++) {
                int r0 = wm + mf * 16 + (lane >> 2);
                int kk = ks + (lane & 3);
                af[mf][0] = As[r0][kk];
                af[mf][1] = As[r0 + 8][kk];
                af[mf][2] = As[r0][kk + 4];
                af[mf][3] = As[r0 + 8][kk + 4];
            }
#pragma unroll
            for (int nf = 0; nf < 4; nf++) {
                int c0 = wn + nf * 8 + (lane >> 2);
                int kk = ks + (lane & 3);
                bf[nf][0] = Bs[c0][kk];
                bf[nf][1] = Bs[c0][kk + 4];
            }
#pragma unroll
            for (int mf = 0; mf < 2; mf++)
#pragma unroll
                for (int nf = 0; nf < 4; nf++)
                    asm volatile(
                        "mma.sync.aligned.m16n8k8.row.col.f32.tf32.tf32.f32 "
                        "{%0,%1,%2,%3}, {%4,%5,%6,%7}, {%8,%9}, {%0,%1,%2,%3};"
                        : "+f"(acc[mf][nf][0]), "+f"(acc[mf][nf][1]),
                          "+f"(acc[mf][nf][2]), "+f"(acc[mf][nf][3])
                        : "r"(af[mf][0]), "r"(af[mf][1]), "r"(af[mf][2]), "r"(af[mf][3]),
                          "r"(bf[nf][0]), "r"(bf[nf][1]));
        }
        __syncthreads();
    }

#pragma unroll
    for (int mf = 0; mf < 2; mf++) {
#pragma unroll
        for (int nf = 0; nf < 4; nf++) {
            int col = bn + wn + nf * 8 + (lane & 3) * 2;
            float b0v = 0.f, b1v = 0.f;
            if (bias) { b0v = bias[col]; b1v = bias[col + 1]; }
            int r0 = bm + wm + mf * 16 + (lane >> 2);
            float v0 = acc[mf][nf][0] + b0v, v1 = acc[mf][nf][1] + b1v;
            float v2 = acc[mf][nf][2] + b0v, v3 = acc[mf][nf][3] + b1v;
            if (relu) {
                v0 = fmaxf(v0, 0.f); v1 = fmaxf(v1, 0.f);
                v2 = fmaxf(v2, 0.f); v3 = fmaxf(v3, 0.f);
            }
            float2 p0; p0.x = v0; p0.y = v1;
            float2 p1; p1.x = v2; p1.y = v3;
            *reinterpret_cast<float2*>(&C[(size_t)r0 * ldc + col]) = p0;
            *reinterpret_cast<float2*>(&C[(size_t)(r0 + 8) * ldc + col]) = p1;
        }
    }
}

// ---------------- fp32 tiled SGEMM (main-loop gh; exact precision) ----------------
__global__ __launch_bounds__(256) void gemm_kernel(
    const float* __restrict__ A, int lda,
    const float* __restrict__ W, int ldw, int wcol0,
    const float* __restrict__ bias,
    float* __restrict__ C, int ldc,
    int K, int relu)
{
    __shared__ float As[16][64];
    __shared__ float Ws[16][64];
    const int bm = blockIdx.x * 64;
    const int bn = blockIdx.y * 64;
    const int tid = threadIdx.x;
    const int tx = tid & 15, ty = tid >> 4;
    const int lm = tid & 63;
    const int lk = (tid >> 6) << 2;

    float acc[4][4] = {};

    const float* Aptr = A + (size_t)(bm + lm) * lda + lk;
    const float* Wptr = W + (size_t)(bn + lm) * ldw + wcol0 + lk;

    for (int k0 = 0; k0 < K; k0 += 16) {
        float4 av = *reinterpret_cast<const float4*>(Aptr + k0);
        float4 wv = *reinterpret_cast<const float4*>(Wptr + k0);
        As[lk + 0][lm] = av.x; As[lk + 1][lm] = av.y;
        As[lk + 2][lm] = av.z; As[lk + 3][lm] = av.w;
        Ws[lk + 0][lm] = wv.x; Ws[lk + 1][lm] = wv.y;
        Ws[lk + 2][lm] = wv.z; Ws[lk + 3][lm] = wv.w;
        __syncthreads();
#pragma unroll
        for (int k = 0; k < 16; k++) {
            float4 a4 = *reinterpret_cast<const float4*>(&As[k][ty << 2]);
            float4 b4 = *reinterpret_cast<const float4*>(&Ws[k][tx << 2]);
            float a[4] = {a4.x, a4.y, a4.z, a4.w};
            float b[4] = {b4.x, b4.y, b4.z, b4.w};
#pragma unroll
            for (int i = 0; i < 4; i++)
#pragma unroll
                for (int j = 0; j < 4; j++)
                    acc[i][j] += a[i] * b[j];
        }
        __syncthreads();
    }

#pragma unroll
    for (int i = 0; i < 4; i++) {
        int row = bm + (ty << 2) + i;
        int col0 = bn + (tx << 2);
        float4 v;
        float vv[4];
#pragma unroll
        for (int j = 0; j < 4; j++) {
            float x = acc[i][j];
            if (bias) x += bias[col0 + j];
            if (relu) x = fmaxf(x, 0.0f);
            vv[j] = x;
        }
        v.x = vv[0]; v.y = vv[1]; v.z = vv[2]; v.w = vv[3];
        *reinterpret_cast<float4*>(&C[(size_t)row * ldc + col0]) = v;
    }
}

// ---------------- elementwise GRU gate kernels ----------------
// encoder: b = roll*1024+n; gi row = n*16 + ((roll + loff) & 15)
__global__ void enc_gate_kernel(const float* __restrict__ Hin,
                                const float* __restrict__ GH,
                                const float* __restrict__ GI,
                                const float* __restrict__ bhh,
                                float* __restrict__ Hout,
                                int loff, int hzero)
{
    int b = blockIdx.x, j = threadIdx.x;
    int n = b & 1023, roll = b >> 10;
    int l = (roll + loff) & 15;
    const float* gi = GI + ((size_t)n * 16 + l) * 768;
    float gr = gi[j], gz = gi[256 + j], gn = gi[512 + j];
    float hr = bhh[j], hz = bhh[256 + j], hn = bhh[512 + j], h = 0.f;
    if (!hzero) {
        const float* gh = GH + (size_t)b * 768;
        hr += gh[j]; hz += gh[256 + j]; hn += gh[512 + j];
        h = Hin[(size_t)b * 256 + j];
    }
    float r = sigm(gr + hr), z = sigm(gz + hz);
    float nn = tanhf(gn + r * hn);
    Hout[(size_t)b * 256 + j] = (1.f - z) * nn + z * h;
}

// main loop: also writes h into out[t,n,4+j]
__global__ void main_gate_kernel(const float* __restrict__ Hin,
                                 const float* __restrict__ GH,
                                 const float* __restrict__ GI,
                                 const float* __restrict__ bhh,
                                 float* __restrict__ Hout,
                                 float* __restrict__ out, int t)
{
    int b = blockIdx.x, j = threadIdx.x;
    const float* gi = GI + ((size_t)t * 1024 + b) * 768;
    const float* gh = GH + (size_t)b * 768;
    float h = Hin[(size_t)b * 256 + j];
    float r = sigm(gi[j] + gh[j] + bhh[j]);
    float z = sigm(gi[256 + j] + gh[256 + j] + bhh[256 + j]);
    float nn = tanhf(gi[512 + j] + r * (gh[512 + j] + bhh[512 + j]));
    float hv = (1.f - z) * nn + z * h;
    Hout[(size_t)b * 256 + j] = hv;
    out[((size_t)t * 1024 + b) * OUTW + 4 + j] = hv;
}

// ---------------- misc small kernels ----------------
__global__ void gather_kernel(const int* __restrict__ lines,
                              const float* __restrict__ embed)
{
    int i = blockIdx.x;                      // 0..16383 = n*L + l
    int line = lines[i];
    S_MFLAT[(size_t)i * 256 + threadIdx.x] = embed[(size_t)line * 256 + threadIdx.x];
}

__global__ void hcat_kernel()
{
    int i = blockIdx.x;                      // 0..16383 = l*N + n (roll-major)
    int t = threadIdx.x;
    S_HCAT[(size_t)i * 512 + t]       = S_E0[(size_t)i * 256 + t];  // hf final
    S_HCAT[(size_t)i * 512 + 256 + t] = S_E2[(size_t)i * 256 + t];  // hb final
}

__global__ void x1_kernel(const int* __restrict__ active,
                          const float* __restrict__ b0)
{
    size_t i = blockIdx.x;                   // 0..262143 = t*N + n
    int n = (int)(i & 1023);
    int w = active[i];
    int h = threadIdx.x;
    float v = S_B1[i * 256 + h] + S_RP[((size_t)w * 1024 + n) * 256 + h] + b0[h];
    S_X1[i * 256 + h] = fmaxf(v, 0.0f);
}

// actor/critic/softmax + packing of a/p/w/pp, reading h back from out
__global__ __launch_bounds__(256) void head_kernel(
    float* __restrict__ out,
    const float* __restrict__ w_actor, const float* __restrict__ b_actor,
    const float* __restrict__ w_critic, const float* __restrict__ b_critic,
    const int* __restrict__ actions, const int* __restrict__ active,
    const float* __restrict__ p0, const float* __restrict__ pp0)
{
    __shared__ float wa[16][257];
    __shared__ float wc[256];
    int tid = threadIdx.x;
    for (int idx = tid; idx < 16 * 256; idx += 256)
        wa[idx >> 8][idx & 255] = w_actor[idx];
    wc[tid] = w_critic[tid];
    __syncthreads();

    int warp = tid >> 5, lane = tid & 31;
#pragma unroll 1
    for (int rr = 0; rr < 4; rr++) {
        size_t row = (size_t)blockIdx.x * 32 + warp * 4 + rr;   // 0..262143
        float* orow = out + row * OUTW;
        const float* hrow = orow + 4;
        const float* wrow = (lane < 16) ? wa[lane] : wc;
        float acc = 0.0f;
#pragma unroll 8
        for (int j = 0; j < 256; j++) acc += hrow[j] * wrow[j];
        if (lane < 16) acc += b_actor[lane];
        else if (lane == 16) acc += b_critic[0];

        // softmax among lanes 0..15
        float lg = (lane < 16) ? acc : -1e30f;
        float m = lg;
#pragma unroll
        for (int o = 8; o > 0; o >>= 1)
            m = fmaxf(m, __shfl_xor_sync(0xffffffffu, m, o, 16));
        float e = expf(lg - m);
        float s = e;
#pragma unroll
        for (int o = 8; o > 0; o >>= 1)
            s += __shfl_xor_sync(0xffffffffu, s, o, 16);
        float p = e / s;

        int n = (int)(row & 1023);
        if (lane < 16)       orow[260 + lane] = p;
        else if (lane == 16) orow[3]   = acc;
        else if (lane == 17) orow[0]   = (float)actions[row];
        else if (lane == 18) orow[1]   = p0[n];
        else if (lane == 19) orow[2]   = (float)active[row];
        else if (lane == 20) orow[276] = pp0[2 * n];
        else if (lane == 21) orow[277] = pp0[2 * n + 1];
    }
}

// ---------------- launcher ----------------
extern "C" void kernel_launch(void* const* d_in, const int* in_sizes, int n_in,
                              void* d_out, int out_size)
{
    const float* condition = (const float*)d_in[0];
    const int*   active    = (const int*)d_in[1];
    const int*   lines     = (const int*)d_in[2];
    const int*   actions   = (const int*)d_in[3];
    const float* h0        = (const float*)d_in[4];
    const float* p0        = (const float*)d_in[5];
    const float* pp0       = (const float*)d_in[6];
    const float* embed     = (const float*)d_in[7];
    const float* wih_f     = (const float*)d_in[8];
    const float* whh_f     = (const float*)d_in[9];
    const float* bih_f     = (const float*)d_in[10];
    const float* bhh_f     = (const float*)d_in[11];
    const float* wih_b     = (const float*)d_in[12];
    const float* whh_b     = (const float*)d_in[13];
    const float* bih_b     = (const float*)d_in[14];
    const float* bhh_b     = (const float*)d_in[15];
    const float* f_w0      = (const float*)d_in[16];
    const float* f_b0      = (const float*)d_in[17];
    const float* f_w1      = (const float*)d_in[18];
    const float* f_b1      = (const float*)d_in[19];
    const float* f_w2      = (const float*)d_in[20];
    const float* f_b2      = (const float*)d_in[21];
    const float* c_wih     = (const float*)d_in[22];
    const float* c_whh     = (const float*)d_in[23];
    const float* c_bih     = (const float*)d_in[24];
    const float* c_bhh     = (const float*)d_in[25];
    const float* w_critic  = (const float*)d_in[26];
    const float* b_critic  = (const float*)d_in[27];
    const float* w_actor   = (const float*)d_in[28];
    const float* b_actor   = (const float*)d_in[29];
    float* out = (float*)d_out;

    float *mflat, *gf, *gb, *gh, *ghm, *e0, *e1, *e2, *e3, *hcat, *rp, *b1, *x1, *x2, *gi, *hh0, *hh1;
    cudaGetSymbolAddress((void**)&mflat, S_MFLAT);
    cudaGetSymbolAddress((void**)&gf,    S_GF);
    cudaGetSymbolAddress((void**)&gb,    S_GB);
    cudaGetSymbolAddress((void**)&gh,    S_GH);
    cudaGetSymbolAddress((void**)&ghm,   S_GHM);
    cudaGetSymbolAddress((void**)&e0,    S_E0);
    cudaGetSymbolAddress((void**)&e1,    S_E1);
    cudaGetSymbolAddress((void**)&e2,    S_E2);
    cudaGetSymbolAddress((void**)&e3,    S_E3);
    cudaGetSymbolAddress((void**)&hcat,  S_HCAT);
    cudaGetSymbolAddress((void**)&rp,    S_RP);
    cudaGetSymbolAddress((void**)&b1,    S_B1);
    cudaGetSymbolAddress((void**)&x1,    S_X1);
    cudaGetSymbolAddress((void**)&x2,    S_X2);
    cudaGetSymbolAddress((void**)&gi,    S_GI);
    cudaGetSymbolAddress((void**)&hh0,   S_H0);
    cudaGetSymbolAddress((void**)&hh1,   S_H1);

    // ---- task encoder ----
    gather_kernel<<<16384, 256>>>(lines, embed);

    // gi precompute over the 16384 distinct (n,l) rows (includes bih)  [tf32 MMA]
    mma_gemm_kernel<<<dim3(128, 12), 256>>>(mflat, 256, wih_f, 256, 0, bih_f, gf, 768, 256, 0);
    mma_gemm_kernel<<<dim3(128, 12), 256>>>(mflat, 256, wih_b, 256, 0, bih_b, gb, 768, 256, 0);

    // forward scan: gh GEMM (tf32) + elementwise gates
    for (int t = 0; t < 16; t++) {
        const float* src = (t & 1) ? e1 : e0;
        float* dst = (t & 1) ? e0 : e1;        // t=15 (odd) -> e0 final
        if (t > 0)
            mma_gemm_kernel<<<dim3(128, 12), 256>>>(src, 256, whh_f, 256, 0, nullptr,
                                                    gh, 768, 256, 0);
        enc_gate_kernel<<<16384, 256>>>(src, gh, gf, bhh_f, dst, t, t == 0);
    }
    // backward scan
    for (int s = 0; s < 16; s++) {
        const float* src = (s & 1) ? e3 : e2;
        float* dst = (s & 1) ? e2 : e3;        // s=15 -> e2 final
        if (s > 0)
            mma_gemm_kernel<<<dim3(128, 12), 256>>>(src, 256, whh_b, 256, 0, nullptr,
                                                    gh, 768, 256, 0);
        enc_gate_kernel<<<16384, 256>>>(src, gh, gb, bhh_b, dst, 15 - s, s == 0);
    }
    hcat_kernel<<<16384, 256>>>();

    // ---- main-loop parallel precompute (all tf32 MMA) ----
    // Rp[l*N+n] = Hmem @ f_w0[:, C:].T
    mma_gemm_kernel<<<dim3(128, 4), 256>>>(hcat, 512, f_w0, 576, 64, nullptr, rp, 256, 512, 0);
    // Acond[t*N+n] = cond @ f_w0[:, :C].T   (into b1)
    mma_gemm_kernel<<<dim3(2048, 4), 256>>>(condition, 64, f_w0, 576, 0, nullptr, b1, 256, 64, 0);
    // x1 = relu(Acond + gather(Rp) + b0)
    x1_kernel<<<262144, 256>>>(active, f_b0);
    // x2 = relu(x1 @ f_w1.T + b1)
    mma_gemm_kernel<<<dim3(2048, 4), 256>>>(x1, 256, f_w1, 256, 0, f_b1, x2, 256, 256, 1);
    // x3 = relu(x2 @ f_w2.T + b2) -> reuse b1
    mma_gemm_kernel<<<dim3(2048, 4), 256>>>(x2, 256, f_w2, 256, 0, f_b2, b1, 256, 256, 1);
    // GI = x3 @ c_wih.T + c_bih
    mma_gemm_kernel<<<dim3(2048, 12), 256>>>(b1, 256, c_wih, 256, 0, c_bih, gi, 768, 256, 0);

    // ---- sequential main loop (fp32 for recurrence stability) ----
    for (int t = 0; t < 256; t++) {
        const float* src = (t == 0) ? h0 : ((t & 1) ? hh0 : hh1);
        float* dst = (t & 1) ? hh1 : hh0;
        gemm_kernel<<<dim3(16, 12), 256>>>(src, 256, c_whh, 256, 0, nullptr,
                                           ghm, 768, 256, 0);
        main_gate_kernel<<<1024, 256>>>(src, ghm, gi, c_bhh, dst, out, t);
    }

    // ---- heads + packing (parallel over all T*N) ----
    head_kernel<<<8192, 256>>>(out, w_actor, b_actor, w_critic, b_critic,
                               actions, active, p0, pp0);
}

// round 3
// speedup vs baseline: 1.9797x; 1.2082x over previous
#include <cuda_runtime.h>
#include <cstdint>
#include <cstdio>

// Problem constants
#define TT   256
#define NN   1024
#define HH   256
#define LLN  16
#define OUTW 278   // 4 + 256 + 16 + 2

#define BM 128
#define BN 128
#define BK 32
#define PAD 36
#define SMEM_BYTES (4 * BM * PAD * 4)   // As[2]+Bs[2], fp32

// ---------------- scratch (device globals; no allocations allowed) ----------------
__device__ float S_MFLAT[16384 * 256];          // embed[lines] rows n*L+l
__device__ float S_GF[16384 * 768];             // forward  gi per distinct (n,l)
__device__ float S_GB[16384 * 768];             // backward gi per distinct (n,l)
__device__ float S_GH[16384 * 768];             // encoder gh scratch
__device__ float S_GHM[1024 * 768];             // main-loop gh scratch
__device__ float S_E0[16384 * 256];             // encoder ping-pong fwd
__device__ float S_E1[16384 * 256];
__device__ float S_E2[16384 * 256];             // encoder ping-pong bwd
__device__ float S_E3[16384 * 256];
__device__ float S_HCAT[16384 * 512];           // concat(hf, hb) rows l*N+n
__device__ float S_RP[16384 * 256];             // f_w0[:,C:] @ Hmem
__device__ float S_B1[262144 * 256];            // Acond, later reused as X3
__device__ float S_X1[262144 * 256];
__device__ float S_X2[262144 * 256];
__device__ float S_GI[(size_t)262144 * 768];    // main-loop gi for all t
__device__ float S_H0[1024 * 256];              // main-loop h ping-pong
__device__ float S_H1[1024 * 256];

__device__ __forceinline__ float sigm(float x) { return 1.0f / (1.0f + expf(-x)); }

__device__ __forceinline__ void cp16(void* sdst, const void* gsrc) {
    unsigned s = (unsigned)__cvta_generic_to_shared(sdst);
    asm volatile("cp.async.cg.shared.global [%0], [%1], 16;" :: "r"(s), "l"(gsrc));
}
__device__ __forceinline__ void cp_commit() {
    asm volatile("cp.async.commit_group;");
}
__device__ __forceinline__ void cp_wait1() {
    asm volatile("cp.async.wait_group 1;");
}

__device__ __forceinline__ void spl(float x, unsigned& hi, unsigned& lo) {
    unsigned b = __float_as_uint(x);
    hi = b & 0xffffe000u;                 // bits the tf32 HW path keeps
    lo = __float_as_uint(x - __uint_as_float(hi));
}

__device__ __forceinline__ void mma8(float* c, const unsigned* a, const unsigned* b) {
    asm volatile(
        "mma.sync.aligned.m16n8k8.row.col.f32.tf32.tf32.f32 "
        "{%0,%1,%2,%3}, {%4,%5,%6,%7}, {%8,%9}, {%0,%1,%2,%3};"
        : "+f"(c[0]), "+f"(c[1]), "+f"(c[2]), "+f"(c[3])
        : "r"(a[0]), "r"(a[1]), "r"(a[2]), "r"(a[3]), "r"(b[0]), "r"(b[1]));
}

// ---------------- tf32 tensor-core GEMM v2: C = op(A @ W^T + bias) ----------------
// A: [M,K] row-major (lda); W rows at W[row*ldw + wcol0 + k]; C: [M,Nc] (ldc).
// Block 128x128, BK=32, cp.async double-buffered. M%128==0, Nc%128==0, K%32==0.
// SPLIT3=1: 3-pass tf32 error compensation (~fp32 accuracy).
template<int SPLIT3>
__global__ __launch_bounds__(256) void mma_v2(
    const float* __restrict__ A, int lda,
    const float* __restrict__ W, int ldw, int wcol0,
    const float* __restrict__ bias,
    float* __restrict__ C, int ldc, int K, int relu)
{
    extern __shared__ float sm[];
    float (*As)[BM][PAD] = (float (*)[BM][PAD])sm;              // [2][128][36]
    float (*Bs)[BN][PAD] = (float (*)[BN][PAD])(sm + 2 * BM * PAD);

    const int tid  = threadIdx.x;
    const int bm   = blockIdx.x * BM;
    const int bn   = blockIdx.y * BN;
    const int lane = tid & 31;
    const int warp = tid >> 5;
    const int wm   = (warp & 1) * 64;
    const int wn   = (warp >> 1) * 32;
    const int lr   = lane >> 2;
    const int lk   = lane & 3;

    const int mld = tid >> 3;          // 0..31
    const int kq  = (tid & 7) * 4;     // 0,4,...,28

    float acc[4][4][4] = {};

    const int KT = K / BK;

    // prologue: prefetch tile 0
    {
        const float* Ab = A + (size_t)bm * lda + kq;
        const float* Wb = W + (size_t)bn * ldw + wcol0 + kq;
#pragma unroll
        for (int j = 0; j < 4; j++) {
            int m = mld + 32 * j;
            cp16(&As[0][m][kq], Ab + (size_t)m * lda);
            cp16(&Bs[0][m][kq], Wb + (size_t)m * ldw);
        }
        cp_commit();
    }

    for (int kt = 0; kt < KT; kt++) {
        const int buf = kt & 1;
        if (kt + 1 < KT) {
            int k0 = (kt + 1) * BK;
            const float* Ab = A + (size_t)bm * lda + k0 + kq;
            const float* Wb = W + (size_t)bn * ldw + wcol0 + k0 + kq;
#pragma unroll
            for (int j = 0; j < 4; j++) {
                int m = mld + 32 * j;
                cp16(&As[buf ^ 1][m][kq], Ab + (size_t)m * lda);
                cp16(&Bs[buf ^ 1][m][kq], Wb + (size_t)m * ldw);
            }
        }
        cp_commit();
        cp_wait1();
        __syncthreads();

#pragma unroll
        for (int ks = 0; ks < BK; ks += 8) {
            unsigned ah[4][4], bh[4][2];
            unsigned al[4][4], bl[4][2];
#pragma unroll
            for (int mf = 0; mf < 4; mf++) {
                int r = wm + mf * 16 + lr;
                float a0 = As[buf][r][ks + lk];
                float a1 = As[buf][r + 8][ks + lk];
                float a2 = As[buf][r][ks + lk + 4];
                float a3 = As[buf][r + 8][ks + lk + 4];
                if (SPLIT3) {
                    spl(a0, ah[mf][0], al[mf][0]); spl(a1, ah[mf][1], al[mf][1]);
                    spl(a2, ah[mf][2], al[mf][2]); spl(a3, ah[mf][3], al[mf][3]);
                } else {
                    ah[mf][0] = __float_as_uint(a0); ah[mf][1] = __float_as_uint(a1);
                    ah[mf][2] = __float_as_uint(a2); ah[mf][3] = __float_as_uint(a3);
                }
            }
#pragma unroll
            for (int nf = 0; nf < 4; nf++) {
                int c = wn + nf * 8 + lr;
                float b0 = Bs[buf][c][ks + lk];
                float b1 = Bs[buf][c][ks + lk + 4];
                if (SPLIT3) {
                    spl(b0, bh[nf][0], bl[nf][0]); spl(b1, bh[nf][1], bl[nf][1]);
                } else {
                    bh[nf][0] = __float_as_uint(b0); bh[nf][1] = __float_as_uint(b1);
                }
            }
#pragma unroll
            for (int mf = 0; mf < 4; mf++)
#pragma unroll
                for (int nf = 0; nf < 4; nf++) {
                    mma8(acc[mf][nf], ah[mf], bh[nf]);
                    if (SPLIT3) {
                        mma8(acc[mf][nf], ah[mf], bl[nf]);
                        mma8(acc[mf][nf], al[mf], bh[nf]);
                    }
                }
        }
        __syncthreads();
    }

#pragma unroll
    for (int mf = 0; mf < 4; mf++) {
#pragma unroll
        for (int nf = 0; nf < 4; nf++) {
            int col = bn + wn + nf * 8 + lk * 2;
            float b0v = 0.f, b1v = 0.f;
            if (bias) { b0v = bias[col]; b1v = bias[col + 1]; }
            int r0 = bm + wm + mf * 16 + lr;
            float v0 = acc[mf][nf][0] + b0v, v1 = acc[mf][nf][1] + b1v;
            float v2 = acc[mf][nf][2] + b0v, v3 = acc[mf][nf][3] + b1v;
            if (relu) {
                v0 = fmaxf(v0, 0.f); v1 = fmaxf(v1, 0.f);
                v2 = fmaxf(v2, 0.f); v3 = fmaxf(v3, 0.f);
            }
            float2 p0; p0.x = v0; p0.y = v1;
            float2 p1; p1.x = v2; p1.y = v3;
            *reinterpret_cast<float2*>(&C[(size_t)r0 * ldc + col]) = p0;
            *reinterpret_cast<float2*>(&C[(size_t)(r0 + 8) * ldc + col]) = p1;
        }
    }
}

// ---------------- elementwise GRU gate kernels ----------------
// encoder: b = roll*1024+n; gi row = n*16 + ((roll + loff) & 15)
__global__ void enc_gate_kernel(const float* __restrict__ Hin,
                                const float* __restrict__ GH,
                                const float* __restrict__ GI,
                                const float* __restrict__ bhh,
                                float* __restrict__ Hout,
                                int loff, int hzero)
{
    int b = blockIdx.x, j = threadIdx.x;
    int n = b & 1023, roll = b >> 10;
    int l = (roll + loff) & 15;
    const float* gi = GI + ((size_t)n * 16 + l) * 768;
    float gr = gi[j], gz = gi[256 + j], gn = gi[512 + j];
    float hr = bhh[j], hz = bhh[256 + j], hn = bhh[512 + j], h = 0.f;
    if (!hzero) {
        const float* gh = GH + (size_t)b * 768;
        hr += gh[j]; hz += gh[256 + j]; hn += gh[512 + j];
        h = Hin[(size_t)b * 256 + j];
    }
    float r = sigm(gr + hr), z = sigm(gz + hz);
    float nn = tanhf(gn + r * hn);
    Hout[(size_t)b * 256 + j] = (1.f - z) * nn + z * h;
}

// main loop: also writes h into out[t,n,4+j]
__global__ void main_gate_kernel(const float* __restrict__ Hin,
                                 const float* __restrict__ GH,
                                 const float* __restrict__ GI,
                                 const float* __restrict__ bhh,
                                 float* __restrict__ Hout,
                                 float* __restrict__ out, int t)
{
    int b = blockIdx.x, j = threadIdx.x;
    const float* gi = GI + ((size_t)t * 1024 + b) * 768;
    const float* gh = GH + (size_t)b * 768;
    float h = Hin[(size_t)b * 256 + j];
    float r = sigm(gi[j] + gh[j] + bhh[j]);
    float z = sigm(gi[256 + j] + gh[256 + j] + bhh[256 + j]);
    float nn = tanhf(gi[512 + j] + r * (gh[512 + j] + bhh[512 + j]));
    float hv = (1.f - z) * nn + z * h;
    Hout[(size_t)b * 256 + j] = hv;
    out[((size_t)t * 1024 + b) * OUTW + 4 + j] = hv;
}

// ---------------- misc small kernels ----------------
__global__ void gather_kernel(const int* __restrict__ lines,
                              const float* __restrict__ embed)
{
    int i = blockIdx.x;                      // 0..16383 = n*L + l
    int line = lines[i];
    S_MFLAT[(size_t)i * 256 + threadIdx.x] = embed[(size_t)line * 256 + threadIdx.x];
}

__global__ void hcat_kernel()
{
    int i = blockIdx.x;                      // 0..16383 = l*N + n (roll-major)
    int t = threadIdx.x;
    S_HCAT[(size_t)i * 512 + t]       = S_E0[(size_t)i * 256 + t];  // hf final
    S_HCAT[(size_t)i * 512 + 256 + t] = S_E2[(size_t)i * 256 + t];  // hb final
}

__global__ void x1_kernel(const int* __restrict__ active,
                          const float* __restrict__ b0)
{
    size_t i = blockIdx.x;                   // 0..262143 = t*N + n
    int n = (int)(i & 1023);
    int w = active[i];
    int h = threadIdx.x;
    float v = S_B1[i * 256 + h] + S_RP[((size_t)w * 1024 + n) * 256 + h] + b0[h];
    S_X1[i * 256 + h] = fmaxf(v, 0.0f);
}

// actor/critic/softmax + packing of a/p/w/pp, reading h back from out
__global__ __launch_bounds__(256) void head_kernel(
    float* __restrict__ out,
    const float* __restrict__ w_actor, const float* __restrict__ b_actor,
    const float* __restrict__ w_critic, const float* __restrict__ b_critic,
    const int* __restrict__ actions, const int* __restrict__ active,
    const float* __restrict__ p0, const float* __restrict__ pp0)
{
    __shared__ float wa[16][257];
    __shared__ float wc[256];
    int tid = threadIdx.x;
    for (int idx = tid; idx < 16 * 256; idx += 256)
        wa[idx >> 8][idx & 255] = w_actor[idx];
    wc[tid] = w_critic[tid];
    __syncthreads();

    int warp = tid >> 5, lane = tid & 31;
#pragma unroll 1
    for (int rr = 0; rr < 4; rr++) {
        size_t row = (size_t)blockIdx.x * 32 + warp * 4 + rr;   // 0..262143
        float* orow = out + row * OUTW;
        const float* hrow = orow + 4;
        const float* wrow = (lane < 16) ? wa[lane] : wc;
        float acc = 0.0f;
#pragma unroll 8
        for (int j = 0; j < 256; j++) acc += hrow[j] * wrow[j];
        if (lane < 16) acc += b_actor[lane];
        else if (lane == 16) acc += b_critic[0];

        // softmax among lanes 0..15
        float lg = (lane < 16) ? acc : -1e30f;
        float m = lg;
#pragma unroll
        for (int o = 8; o > 0; o >>= 1)
            m = fmaxf(m, __shfl_xor_sync(0xffffffffu, m, o, 16));
        float e = expf(lg - m);
        float s = e;
#pragma unroll
        for (int o = 8; o > 0; o >>= 1)
            s += __shfl_xor_sync(0xffffffffu, s, o, 16);
        float p = e / s;

        int n = (int)(row & 1023);
        if (lane < 16)       orow[260 + lane] = p;
        else if (lane == 16) orow[3]   = acc;
        else if (lane == 17) orow[0]   = (float)actions[row];
        else if (lane == 18) orow[1]   = p0[n];
        else if (lane == 19) orow[2]   = (float)active[row];
        else if (lane == 20) orow[276] = pp0[2 * n];
        else if (lane == 21) orow[277] = pp0[2 * n + 1];
    }
}

// ---------------- launcher ----------------
extern "C" void kernel_launch(void* const* d_in, const int* in_sizes, int n_in,
                              void* d_out, int out_size)
{
    const float* condition = (const float*)d_in[0];
    const int*   active    = (const int*)d_in[1];
    const int*   lines     = (const int*)d_in[2];
    const int*   actions   = (const int*)d_in[3];
    const float* h0        = (const float*)d_in[4];
    const float* p0        = (const float*)d_in[5];
    const float* pp0       = (const float*)d_in[6];
    const float* embed     = (const float*)d_in[7];
    const float* wih_f     = (const float*)d_in[8];
    const float* whh_f     = (const float*)d_in[9];
    const float* bih_f     = (const float*)d_in[10];
    const float* bhh_f     = (const float*)d_in[11];
    const float* wih_b     = (const float*)d_in[12];
    const float* whh_b     = (const float*)d_in[13];
    const float* bih_b     = (const float*)d_in[14];
    const float* bhh_b     = (const float*)d_in[15];
    const float* f_w0      = (const float*)d_in[16];
    const float* f_b0      = (const float*)d_in[17];
    const float* f_w1      = (const float*)d_in[18];
    const float* f_b1      = (const float*)d_in[19];
    const float* f_w2      = (const float*)d_in[20];
    const float* f_b2      = (const float*)d_in[21];
    const float* c_wih     = (const float*)d_in[22];
    const float* c_whh     = (const float*)d_in[23];
    const float* c_bih     = (const float*)d_in[24];
    const float* c_bhh     = (const float*)d_in[25];
    const float* w_critic  = (const float*)d_in[26];
    const float* b_critic  = (const float*)d_in[27];
    const float* w_actor   = (const float*)d_in[28];
    const float* b_actor   = (const float*)d_in[29];
    float* out = (float*)d_out;

    float *mflat, *gf, *gb, *gh, *ghm, *e0, *e1, *e2, *e3, *hcat, *rp, *b1, *x1, *x2, *gi, *hh0, *hh1;
    cudaGetSymbolAddress((void**)&mflat, S_MFLAT);
    cudaGetSymbolAddress((void**)&gf,    S_GF);
    cudaGetSymbolAddress((void**)&gb,    S_GB);
    cudaGetSymbolAddress((void**)&gh,    S_GH);
    cudaGetSymbolAddress((void**)&ghm,   S_GHM);
    cudaGetSymbolAddress((void**)&e0,    S_E0);
    cudaGetSymbolAddress((void**)&e1,    S_E1);
    cudaGetSymbolAddress((void**)&e2,    S_E2);
    cudaGetSymbolAddress((void**)&e3,    S_E3);
    cudaGetSymbolAddress((void**)&hcat,  S_HCAT);
    cudaGetSymbolAddress((void**)&rp,    S_RP);
    cudaGetSymbolAddress((void**)&b1,    S_B1);
    cudaGetSymbolAddress((void**)&x1,    S_X1);
    cudaGetSymbolAddress((void**)&x2,    S_X2);
    cudaGetSymbolAddress((void**)&gi,    S_GI);
    cudaGetSymbolAddress((void**)&hh0,   S_H0);
    cudaGetSymbolAddress((void**)&hh1,   S_H1);

    cudaFuncSetAttribute(mma_v2<0>, cudaFuncAttributeMaxDynamicSharedMemorySize, SMEM_BYTES);
    cudaFuncSetAttribute(mma_v2<1>, cudaFuncAttributeMaxDynamicSharedMemorySize, SMEM_BYTES);

    // ---- task encoder ----
    gather_kernel<<<16384, 256>>>(lines, embed);

    // gi precompute over the 16384 distinct (n,l) rows (includes bih)
    mma_v2<0><<<dim3(128, 6), 256, SMEM_BYTES>>>(mflat, 256, wih_f, 256, 0, bih_f, gf, 768, 256, 0);
    mma_v2<0><<<dim3(128, 6), 256, SMEM_BYTES>>>(mflat, 256, wih_b, 256, 0, bih_b, gb, 768, 256, 0);

    // forward scan: gh GEMM (tf32) + elementwise gates
    for (int t = 0; t < 16; t++) {
        const float* src = (t & 1) ? e1 : e0;
        float* dst = (t & 1) ? e0 : e1;        // t=15 (odd) -> e0 final
        if (t > 0)
            mma_v2<0><<<dim3(128, 6), 256, SMEM_BYTES>>>(src, 256, whh_f, 256, 0, nullptr,
                                                         gh, 768, 256, 0);
        enc_gate_kernel<<<16384, 256>>>(src, gh, gf, bhh_f, dst, t, t == 0);
    }
    // backward scan
    for (int s = 0; s < 16; s++) {
        const float* src = (s & 1) ? e3 : e2;
        float* dst = (s & 1) ? e2 : e3;        // s=15 -> e2 final
        if (s > 0)
            mma_v2<0><<<dim3(128, 6), 256, SMEM_BYTES>>>(src, 256, whh_b, 256, 0, nullptr,
                                                         gh, 768, 256, 0);
        enc_gate_kernel<<<16384, 256>>>(src, gh, gb, bhh_b, dst, 15 - s, s == 0);
    }
    hcat_kernel<<<16384, 256>>>();

    // ---- main-loop parallel precompute ----
    // Rp[l*N+n] = Hmem @ f_w0[:, C:].T   (K=512)
    mma_v2<0><<<dim3(128, 2), 256, SMEM_BYTES>>>(hcat, 512, f_w0, 576, 64, nullptr, rp, 256, 512, 0);
    // Acond[t*N+n] = cond @ f_w0[:, :C].T   (K=64, into b1)
    mma_v2<0><<<dim3(2048, 2), 256, SMEM_BYTES>>>(condition, 64, f_w0, 576, 0, nullptr, b1, 256, 64, 0);
    // x1 = relu(Acond + gather(Rp) + b0)
    x1_kernel<<<262144, 256>>>(active, f_b0);
    // x2 = relu(x1 @ f_w1.T + b1)
    mma_v2<0><<<dim3(2048, 2), 256, SMEM_BYTES>>>(x1, 256, f_w1, 256, 0, f_b1, x2, 256, 256, 1);
    // x3 = relu(x2 @ f_w2.T + b2) -> reuse b1
    mma_v2<0><<<dim3(2048, 2), 256, SMEM_BYTES>>>(x2, 256, f_w2, 256, 0, f_b2, b1, 256, 256, 1);
    // GI = x3 @ c_wih.T + c_bih
    mma_v2<0><<<dim3(2048, 6), 256, SMEM_BYTES>>>(b1, 256, c_wih, 256, 0, c_bih, gi, 768, 256, 0);

    // ---- sequential main loop: 3xTF32 tensor-core gh + gates ----
    for (int t = 0; t < 256; t++) {
        const float* src = (t == 0) ? h0 : ((t & 1) ? hh0 : hh1);
        float* dst = (t & 1) ? hh1 : hh0;
        mma_v2<1><<<dim3(8, 6), 256, SMEM_BYTES>>>(src, 256, c_whh, 256, 0, nullptr,
                                                   ghm, 768, 256, 0);
        main_gate_kernel<<<1024, 256>>>(src, ghm, gi, c_bhh, dst, out, t);
    }

    // ---- heads + packing (parallel over all T*N) ----
    head_kernel<<<8192, 256>>>(out, w_actor, b_actor, w_critic, b_critic,
                               actions, active, p0, pp0);
}

// round 4
// speedup vs baseline: 2.0139x; 1.0173x over previous
#include <cuda_runtime.h>
#include <cstdint>
#include <cstdio>

// Problem constants
#define TT   256
#define NN   1024
#define HH   256
#define OUTW 278   // 4 + 256 + 16 + 2

#define SMEM128 69632   // 2 bufs * (128+128) rows * 34 floats * 4B
#define SMEM64  34816   // 2 bufs * (64+64)  rows * 34 floats * 4B

// ---------------- scratch (device globals; no allocations allowed) ----------------
__device__ float S_MFLAT[16384 * 256];          // embed[lines] rows n*L+l
__device__ float S_GF[16384 * 768];             // forward  gi per distinct (n,l)
__device__ float S_GB[16384 * 768];             // backward gi per distinct (n,l)
__device__ float S_GH[16384 * 768];             // encoder gh scratch
__device__ float S_GHM[1024 * 768];             // main-loop gh scratch
__device__ float S_E0[16384 * 256];             // encoder ping-pong fwd
__device__ float S_E1[16384 * 256];
__device__ float S_E2[16384 * 256];             // encoder ping-pong bwd
__device__ float S_E3[16384 * 256];
__device__ float S_HCAT[16384 * 512];           // concat(hf, hb) rows l*N+n
__device__ float S_RP[16384 * 256];             // f_w0[:,C:] @ Hmem
__device__ float S_B1[262144 * 256];            // Acond, later reused as X3
__device__ float S_X1[262144 * 256];
__device__ float S_X2[262144 * 256];
__device__ float S_GI[(size_t)262144 * 768];    // main-loop gi for all t
__device__ float S_H0[1024 * 256];              // main-loop h ping-pong
__device__ float S_H1[1024 * 256];

__device__ __forceinline__ float sigm(float x) { return 1.0f / (1.0f + expf(-x)); }

__device__ __forceinline__ void spl(float x, unsigned& hi, unsigned& lo) {
    unsigned b = __float_as_uint(x);
    hi = b & 0xffffe000u;                 // bits the tf32 HW path keeps
    lo = __float_as_uint(x - __uint_as_float(hi));
}

__device__ __forceinline__ void mma8(float* c, const unsigned* a, const unsigned* b) {
    asm volatile(
        "mma.sync.aligned.m16n8k8.row.col.f32.tf32.tf32.f32 "
        "{%0,%1,%2,%3}, {%4,%5,%6,%7}, {%8,%9}, {%0,%1,%2,%3};"
        : "+f"(c[0]), "+f"(c[1]), "+f"(c[2]), "+f"(c[3])
        : "r"(a[0]), "r"(a[1]), "r"(a[2]), "r"(a[3]), "r"(b[0]), "r"(b[1]));
}

// ---------------- tf32 tensor-core GEMM v3: C = op(A @ W^T + bias) ----------------
// A: [M,K] row-major (lda); W rows at W[row*ldw + wcol0 + k]; C: [M,Nc] (ldc).
// k-permuted smem layout: pk = (k&3)*8 + (k>>2), row stride 34 floats.
// Thread's fragment k-values (k, k+4) are adjacent -> LDS.64 per fragment pair.
// 8 warps (4M x 2N). M%BMT==0, Nc%BNT==0, K%32==0.
template<int SPLIT3, int BMT, int BNT>
__global__ __launch_bounds__(256) void mma_v3(
    const float* __restrict__ A, int lda,
    const float* __restrict__ W, int ldw, int wcol0,
    const float* __restrict__ bias,
    float* __restrict__ C, int ldc, int K, int relu)
{
    constexpr int WTM = BMT / 4, WTN = BNT / 2;
    constexpr int MF  = WTM / 16, NF = WTN / 8;
    constexpr int AJ  = BMT / 32, BJ = BNT / 32;
    constexpr int SA  = BMT * 34, SB = BNT * 34;
    extern __shared__ float sm[];
    float* AsBase = sm;              // [2][BMT][34]
    float* BsBase = sm + 2 * SA;     // [2][BNT][34]

    const int tid  = threadIdx.x;
    const int lane = tid & 31, warp = tid >> 5;
    const int bm = blockIdx.x * BMT, bn = blockIdx.y * BNT;
    const int wm = (warp & 3) * WTM, wn = (warp >> 2) * WTN;
    const int lr = lane >> 2, lk = lane & 3;
    const int mld = tid >> 3, g = tid & 7;      // loader: row tid>>3, k-quad g*4

    float acc[MF][NF][4] = {};
    const int KT = K / 32;

    float4 av[AJ], wv[BJ];

    // prologue: load + store tile 0
    {
        const float* Ab = A + (size_t)(bm + mld) * lda + g * 4;
        const float* Wb = W + (size_t)(bn + mld) * ldw + wcol0 + g * 4;
#pragma unroll
        for (int j = 0; j < AJ; j++) av[j] = *(const float4*)(Ab + (size_t)(32 * j) * lda);
#pragma unroll
        for (int j = 0; j < BJ; j++) wv[j] = *(const float4*)(Wb + (size_t)(32 * j) * ldw);
#pragma unroll
        for (int j = 0; j < AJ; j++) {
            float* p = AsBase + (mld + 32 * j) * 34 + g;
            p[0] = av[j].x; p[8] = av[j].y; p[16] = av[j].z; p[24] = av[j].w;
        }
#pragma unroll
        for (int j = 0; j < BJ; j++) {
            float* p = BsBase + (mld + 32 * j) * 34 + g;
            p[0] = wv[j].x; p[8] = wv[j].y; p[16] = wv[j].z; p[24] = wv[j].w;
        }
    }

    for (int kt = 0; kt < KT; kt++) {
        __syncthreads();
        const int buf = kt & 1;
        if (kt + 1 < KT) {
            int k0 = (kt + 1) * 32;
            const float* Ab = A + (size_t)(bm + mld) * lda + k0 + g * 4;
            const float* Wb = W + (size_t)(bn + mld) * ldw + wcol0 + k0 + g * 4;
#pragma unroll
            for (int j = 0; j < AJ; j++) av[j] = *(const float4*)(Ab + (size_t)(32 * j) * lda);
#pragma unroll
            for (int j = 0; j < BJ; j++) wv[j] = *(const float4*)(Wb + (size_t)(32 * j) * ldw);
        }

        const float* Ab = AsBase + buf * SA;
        const float* Bb = BsBase + buf * SB;
#pragma unroll
        for (int s = 0; s < 4; s++) {
            unsigned ah[MF][4], al[MF][4], bh[NF][2], bl[NF][2];
#pragma unroll
            for (int mf = 0; mf < MF; mf++) {
                int r0 = wm + mf * 16 + lr;
                float2 x0 = *(const float2*)(Ab + r0 * 34 + lk * 8 + 2 * s);
                float2 x1 = *(const float2*)(Ab + (r0 + 8) * 34 + lk * 8 + 2 * s);
                if (SPLIT3) {
                    spl(x0.x, ah[mf][0], al[mf][0]); spl(x1.x, ah[mf][1], al[mf][1]);
                    spl(x0.y, ah[mf][2], al[mf][2]); spl(x1.y, ah[mf][3], al[mf][3]);
                } else {
                    ah[mf][0] = __float_as_uint(x0.x); ah[mf][1] = __float_as_uint(x1.x);
                    ah[mf][2] = __float_as_uint(x0.y); ah[mf][3] = __float_as_uint(x1.y);
                }
            }
#pragma unroll
            for (int nf = 0; nf < NF; nf++) {
                int c0 = wn + nf * 8 + lr;
                float2 y = *(const float2*)(Bb + c0 * 34 + lk * 8 + 2 * s);
                if (SPLIT3) {
                    spl(y.x, bh[nf][0], bl[nf][0]); spl(y.y, bh[nf][1], bl[nf][1]);
                } else {
                    bh[nf][0] = __float_as_uint(y.x); bh[nf][1] = __float_as_uint(y.y);
                }
            }
#pragma unroll
            for (int mf = 0; mf < MF; mf++)
#pragma unroll
                for (int nf = 0; nf < NF; nf++) {
                    mma8(acc[mf][nf], ah[mf], bh[nf]);
                    if (SPLIT3) {
                        mma8(acc[mf][nf], ah[mf], bl[nf]);
                        mma8(acc[mf][nf], al[mf], bh[nf]);
                    }
                }
        }

        if (kt + 1 < KT) {
            float* Ad = AsBase + (buf ^ 1) * SA;
            float* Bd = BsBase + (buf ^ 1) * SB;
#pragma unroll
            for (int j = 0; j < AJ; j++) {
                float* p = Ad + (mld + 32 * j) * 34 + g;
                p[0] = av[j].x; p[8] = av[j].y; p[16] = av[j].z; p[24] = av[j].w;
            }
#pragma unroll
            for (int j = 0; j < BJ; j++) {
                float* p = Bd + (mld + 32 * j) * 34 + g;
                p[0] = wv[j].x; p[8] = wv[j].y; p[16] = wv[j].z; p[24] = wv[j].w;
            }
        }
    }

#pragma unroll
    for (int mf = 0; mf < MF; mf++) {
#pragma unroll
        for (int nf = 0; nf < NF; nf++) {
            int col = bn + wn + nf * 8 + lk * 2;
            float b0v = 0.f, b1v = 0.f;
            if (bias) { b0v = bias[col]; b1v = bias[col + 1]; }
            int r0 = bm + wm + mf * 16 + lr;
            float v0 = acc[mf][nf][0] + b0v, v1 = acc[mf][nf][1] + b1v;
            float v2 = acc[mf][nf][2] + b0v, v3 = acc[mf][nf][3] + b1v;
            if (relu) {
                v0 = fmaxf(v0, 0.f); v1 = fmaxf(v1, 0.f);
                v2 = fmaxf(v2, 0.f); v3 = fmaxf(v3, 0.f);
            }
            float2 p0; p0.x = v0; p0.y = v1;
            float2 p1; p1.x = v2; p1.y = v3;
            *reinterpret_cast<float2*>(&C[(size_t)r0 * ldc + col]) = p0;
            *reinterpret_cast<float2*>(&C[(size_t)(r0 + 8) * ldc + col]) = p1;
        }
    }
}

// ---------------- elementwise GRU gate kernels (float4) ----------------
// encoder: b = roll*1024+n; gi row = n*16 + ((roll + loff) & 15)
__global__ void enc_gate_kernel(const float* __restrict__ Hin,
                                const float* __restrict__ GH,
                                const float* __restrict__ GI,
                                const float* __restrict__ bhh,
                                float* __restrict__ Hout,
                                int loff, int hzero)
{
    int b = blockIdx.x * 4 + (threadIdx.x >> 6);
    int j = (threadIdx.x & 63) * 4;
    int n = b & 1023, roll = b >> 10;
    int l = (roll + loff) & 15;
    const float* gi = GI + ((size_t)n * 16 + l) * 768;
    float4 gr = *(const float4*)(gi + j);
    float4 gz = *(const float4*)(gi + 256 + j);
    float4 gn = *(const float4*)(gi + 512 + j);
    float4 hr = *(const float4*)(bhh + j);
    float4 hz = *(const float4*)(bhh + 256 + j);
    float4 hn = *(const float4*)(bhh + 512 + j);
    float4 h = make_float4(0.f, 0.f, 0.f, 0.f);
    if (!hzero) {
        const float* gh = GH + (size_t)b * 768;
        float4 t;
        t = *(const float4*)(gh + j);       hr.x += t.x; hr.y += t.y; hr.z += t.z; hr.w += t.w;
        t = *(const float4*)(gh + 256 + j); hz.x += t.x; hz.y += t.y; hz.z += t.z; hz.w += t.w;
        t = *(const float4*)(gh + 512 + j); hn.x += t.x; hn.y += t.y; hn.z += t.z; hn.w += t.w;
        h = *(const float4*)(Hin + (size_t)b * 256 + j);
    }
    float4 o;
    {
        float r = sigm(gr.x + hr.x), z = sigm(gz.x + hz.x);
        o.x = (1.f - z) * tanhf(gn.x + r * hn.x) + z * h.x;
    }
    {
        float r = sigm(gr.y + hr.y), z = sigm(gz.y + hz.y);
        o.y = (1.f - z) * tanhf(gn.y + r * hn.y) + z * h.y;
    }
    {
        float r = sigm(gr.z + hr.z), z = sigm(gz.z + hz.z);
        o.z = (1.f - z) * tanhf(gn.z + r * hn.z) + z * h.z;
    }
    {
        float r = sigm(gr.w + hr.w), z = sigm(gz.w + hz.w);
        o.w = (1.f - z) * tanhf(gn.w + r * hn.w) + z * h.w;
    }
    *(float4*)(Hout + (size_t)b * 256 + j) = o;
}

// main loop: also writes h into out[t,n,4+j]
__global__ void main_gate_kernel(const float* __restrict__ Hin,
                                 const float* __restrict__ GH,
                                 const float* __restrict__ GI,
                                 const float* __restrict__ bhh,
                                 float* __restrict__ Hout,
                                 float* __restrict__ out, int t)
{
    int b = blockIdx.x * 4 + (threadIdx.x >> 6);
    int j = (threadIdx.x & 63) * 4;
    const float* gi = GI + ((size_t)t * 1024 + b) * 768;
    const float* gh = GH + (size_t)b * 768;
    float4 gr = *(const float4*)(gi + j);
    float4 gz = *(const float4*)(gi + 256 + j);
    float4 gn = *(const float4*)(gi + 512 + j);
    float4 qr = *(const float4*)(gh + j);
    float4 qz = *(const float4*)(gh + 256 + j);
    float4 qn = *(const float4*)(gh + 512 + j);
    float4 br = *(const float4*)(bhh + j);
    float4 bz = *(const float4*)(bhh + 256 + j);
    float4 bn = *(const float4*)(bhh + 512 + j);
    float4 h = *(const float4*)(Hin + (size_t)b * 256 + j);
    float4 o;
    {
        float r = sigm(gr.x + qr.x + br.x), z = sigm(gz.x + qz.x + bz.x);
        o.x = (1.f - z) * tanhf(gn.x + r * (qn.x + bn.x)) + z * h.x;
    }
    {
        float r = sigm(gr.y + qr.y + br.y), z = sigm(gz.y + qz.y + bz.y);
        o.y = (1.f - z) * tanhf(gn.y + r * (qn.y + bn.y)) + z * h.y;
    }
    {
        float r = sigm(gr.z + qr.z + br.z), z = sigm(gz.z + qz.z + bz.z);
        o.z = (1.f - z) * tanhf(gn.z + r * (qn.z + bn.z)) + z * h.z;
    }
    {
        float r = sigm(gr.w + qr.w + br.w), z = sigm(gz.w + qz.w + bz.w);
        o.w = (1.f - z) * tanhf(gn.w + r * (qn.w + bn.w)) + z * h.w;
    }
    *(float4*)(Hout + (size_t)b * 256 + j) = o;
    float* orow = out + ((size_t)t * 1024 + b) * OUTW + 4 + j;
    float2 w0; w0.x = o.x; w0.y = o.y;
    float2 w1; w1.x = o.z; w1.y = o.w;
    *(float2*)orow = w0;
    *(float2*)(orow + 2) = w1;
}

// ---------------- misc small kernels (float4) ----------------
__global__ void gather_kernel(const int* __restrict__ lines,
                              const float* __restrict__ embed)
{
    int gid = blockIdx.x * 256 + threadIdx.x;
    int e = gid * 4;
    int row = e >> 8, j = e & 255;              // row = n*L+l
    int line = lines[row];
    *(float4*)(S_MFLAT + (size_t)row * 256 + j) =
        *(const float4*)(embed + (size_t)line * 256 + j);
}

__global__ void hcat_kernel()
{
    int gid = blockIdx.x * 256 + threadIdx.x;
    int e = gid * 4;
    int row = e >> 9, c = e & 511;              // row = l*N+n
    float4 v;
    if (c < 256) v = *(const float4*)(S_E0 + (size_t)row * 256 + c);
    else         v = *(const float4*)(S_E2 + (size_t)row * 256 + c - 256);
    *(float4*)(S_HCAT + (size_t)row * 512 + c) = v;
}

__global__ void x1_kernel(const int* __restrict__ active,
                          const float* __restrict__ b0)
{
    size_t gid = (size_t)blockIdx.x * 256 + threadIdx.x;
    size_t e = gid * 4;
    size_t row = e >> 8;                        // t*N + n
    int j = (int)(e & 255);
    int n = (int)(row & 1023);
    int w = active[row];
    float4 a = *(const float4*)(S_B1 + row * 256 + j);
    float4 r = *(const float4*)(S_RP + ((size_t)w * 1024 + n) * 256 + j);
    float4 b = *(const float4*)(b0 + j);
    float4 o;
    o.x = fmaxf(a.x + r.x + b.x, 0.f);
    o.y = fmaxf(a.y + r.y + b.y, 0.f);
    o.z = fmaxf(a.z + r.z + b.z, 0.f);
    o.w = fmaxf(a.w + r.w + b.w, 0.f);
    *(float4*)(S_X1 + row * 256 + j) = o;
}

// actor/critic/softmax + packing of a/p/w/pp, reading h back from out
__global__ __launch_bounds__(256) void head_kernel(
    float* __restrict__ out,
    const float* __restrict__ w_actor, const float* __restrict__ b_actor,
    const float* __restrict__ w_critic, const float* __restrict__ b_critic,
    const int* __restrict__ actions, const int* __restrict__ active,
    const float* __restrict__ p0, const float* __restrict__ pp0)
{
    __shared__ float wa[16][257];
    __shared__ float wc[256];
    int tid = threadIdx.x;
    for (int idx = tid; idx < 16 * 256; idx += 256)
        wa[idx >> 8][idx & 255] = w_actor[idx];
    wc[tid] = w_critic[tid];
    __syncthreads();

    int warp = tid >> 5, lane = tid & 31;
#pragma unroll 1
    for (int rr = 0; rr < 4; rr++) {
        size_t row = (size_t)blockIdx.x * 32 + warp * 4 + rr;   // 0..262143
        float* orow = out + row * OUTW;
        const float* hrow = orow + 4;
        const float* wrow = (lane < 16) ? wa[lane] : wc;
        float acc = 0.0f;
#pragma unroll 8
        for (int j = 0; j < 256; j++) acc += hrow[j] * wrow[j];
        if (lane < 16) acc += b_actor[lane];
        else if (lane == 16) acc += b_critic[0];

        // softmax among lanes 0..15
        float lg = (lane < 16) ? acc : -1e30f;
        float m = lg;
#pragma unroll
        for (int o = 8; o > 0; o >>= 1)
            m = fmaxf(m, __shfl_xor_sync(0xffffffffu, m, o, 16));
        float e = expf(lg - m);
        float s = e;
#pragma unroll
        for (int o = 8; o > 0; o >>= 1)
            s += __shfl_xor_sync(0xffffffffu, s, o, 16);
        float p = e / s;

        int n = (int)(row & 1023);
        if (lane < 16)       orow[260 + lane] = p;
        else if (lane == 16) orow[3]   = acc;
        else if (lane == 17) orow[0]   = (float)actions[row];
        else if (lane == 18) orow[1]   = p0[n];
        else if (lane == 19) orow[2]   = (float)active[row];
        else if (lane == 20) orow[276] = pp0[2 * n];
        else if (lane == 21) orow[277] = pp0[2 * n + 1];
    }
}

// ---------------- launcher ----------------
extern "C" void kernel_launch(void* const* d_in, const int* in_sizes, int n_in,
                              void* d_out, int out_size)
{
    const float* condition = (const float*)d_in[0];
    const int*   active    = (const int*)d_in[1];
    const int*   lines     = (const int*)d_in[2];
    const int*   actions   = (const int*)d_in[3];
    const float* h0        = (const float*)d_in[4];
    const float* p0        = (const float*)d_in[5];
    const float* pp0       = (const float*)d_in[6];
    const float* embed     = (const float*)d_in[7];
    const float* wih_f     = (const float*)d_in[8];
    const float* whh_f     = (const float*)d_in[9];
    const float* bih_f     = (const float*)d_in[10];
    const float* bhh_f     = (const float*)d_in[11];
    const float* wih_b     = (const float*)d_in[12];
    const float* whh_b     = (const float*)d_in[13];
    const float* bih_b     = (const float*)d_in[14];
    const float* bhh_b     = (const float*)d_in[15];
    const float* f_w0      = (const float*)d_in[16];
    const float* f_b0      = (const float*)d_in[17];
    const float* f_w1      = (const float*)d_in[18];
    const float* f_b1      = (const float*)d_in[19];
    const float* f_w2      = (const float*)d_in[20];
    const float* f_b2      = (const float*)d_in[21];
    const float* c_wih     = (const float*)d_in[22];
    const float* c_whh     = (const float*)d_in[23];
    const float* c_bih     = (const float*)d_in[24];
    const float* c_bhh     = (const float*)d_in[25];
    const float* w_critic  = (const float*)d_in[26];
    const float* b_critic  = (const float*)d_in[27];
    const float* w_actor   = (const float*)d_in[28];
    const float* b_actor   = (const float*)d_in[29];
    float* out = (float*)d_out;

    float *mflat, *gf, *gb, *gh, *ghm, *e0, *e1, *e2, *e3, *hcat, *rp, *b1, *x1, *x2, *gi, *hh0, *hh1;
    cudaGetSymbolAddress((void**)&mflat, S_MFLAT);
    cudaGetSymbolAddress((void**)&gf,    S_GF);
    cudaGetSymbolAddress((void**)&gb,    S_GB);
    cudaGetSymbolAddress((void**)&gh,    S_GH);
    cudaGetSymbolAddress((void**)&ghm,   S_GHM);
    cudaGetSymbolAddress((void**)&e0,    S_E0);
    cudaGetSymbolAddress((void**)&e1,    S_E1);
    cudaGetSymbolAddress((void**)&e2,    S_E2);
    cudaGetSymbolAddress((void**)&e3,    S_E3);
    cudaGetSymbolAddress((void**)&hcat,  S_HCAT);
    cudaGetSymbolAddress((void**)&rp,    S_RP);
    cudaGetSymbolAddress((void**)&b1,    S_B1);
    cudaGetSymbolAddress((void**)&x1,    S_X1);
    cudaGetSymbolAddress((void**)&x2,    S_X2);
    cudaGetSymbolAddress((void**)&gi,    S_GI);
    cudaGetSymbolAddress((void**)&hh0,   S_H0);
    cudaGetSymbolAddress((void**)&hh1,   S_H1);

    cudaFuncSetAttribute(mma_v3<0, 128, 128>, cudaFuncAttributeMaxDynamicSharedMemorySize, SMEM128);
    cudaFuncSetAttribute(mma_v3<1, 64, 64>,   cudaFuncAttributeMaxDynamicSharedMemorySize, SMEM64);

    // ---- task encoder ----
    gather_kernel<<<4096, 256>>>(lines, embed);

    // gi precompute over the 16384 distinct (n,l) rows (includes bih)
    mma_v3<0, 128, 128><<<dim3(128, 6), 256, SMEM128>>>(mflat, 256, wih_f, 256, 0, bih_f, gf, 768, 256, 0);
    mma_v3<0, 128, 128><<<dim3(128, 6), 256, SMEM128>>>(mflat, 256, wih_b, 256, 0, bih_b, gb, 768, 256, 0);

    // forward scan: gh GEMM (tf32) + elementwise gates
    for (int t = 0; t < 16; t++) {
        const float* src = (t & 1) ? e1 : e0;
        float* dst = (t & 1) ? e0 : e1;        // t=15 (odd) -> e0 final
        if (t > 0)
            mma_v3<0, 128, 128><<<dim3(128, 6), 256, SMEM128>>>(src, 256, whh_f, 256, 0, nullptr,
                                                                gh, 768, 256, 0);
        enc_gate_kernel<<<4096, 256>>>(src, gh, gf, bhh_f, dst, t, t == 0);
    }
    // backward scan
    for (int s = 0; s < 16; s++) {
        const float* src = (s & 1) ? e3 : e2;
        float* dst = (s & 1) ? e2 : e3;        // s=15 -> e2 final
        if (s > 0)
            mma_v3<0, 128, 128><<<dim3(128, 6), 256, SMEM128>>>(src, 256, whh_b, 256, 0, nullptr,
                                                                gh, 768, 256, 0);
        enc_gate_kernel<<<4096, 256>>>(src, gh, gb, bhh_b, dst, 15 - s, s == 0);
    }
    hcat_kernel<<<8192, 256>>>();

    // ---- main-loop parallel precompute ----
    // Rp[l*N+n] = Hmem @ f_w0[:, C:].T   (K=512)
    mma_v3<0, 128, 128><<<dim3(128, 2), 256, SMEM128>>>(hcat, 512, f_w0, 576, 64, nullptr, rp, 256, 512, 0);
    // Acond[t*N+n] = cond @ f_w0[:, :C].T   (K=64, into b1)
    mma_v3<0, 128, 128><<<dim3(2048, 2), 256, SMEM128>>>(condition, 64, f_w0, 576, 0, nullptr, b1, 256, 64, 0);
    // x1 = relu(Acond + gather(Rp) + b0)
    x1_kernel<<<65536, 256>>>(active, f_b0);
    // x2 = relu(x1 @ f_w1.T + b1)
    mma_v3<0, 128, 128><<<dim3(2048, 2), 256, SMEM128>>>(x1, 256, f_w1, 256, 0, f_b1, x2, 256, 256, 1);
    // x3 = relu(x2 @ f_w2.T + b2) -> reuse b1
    mma_v3<0, 128, 128><<<dim3(2048, 2), 256, SMEM128>>>(x2, 256, f_w2, 256, 0, f_b2, b1, 256, 256, 1);
    // GI = x3 @ c_wih.T + c_bih
    mma_v3<0, 128, 128><<<dim3(2048, 6), 256, SMEM128>>>(b1, 256, c_wih, 256, 0, c_bih, gi, 768, 256, 0);

    // ---- sequential main loop: split3 tf32 gh (fp32-grade) + gates ----
    for (int t = 0; t < 256; t++) {
        const float* src = (t == 0) ? h0 : ((t & 1) ? hh0 : hh1);
        float* dst = (t & 1) ? hh1 : hh0;
        mma_v3<1, 64, 64><<<dim3(16, 12), 256, SMEM64>>>(src, 256, c_whh, 256, 0, nullptr,
                                                         ghm, 768, 256, 0);
        main_gate_kernel<<<256, 256>>>(src, ghm, gi, c_bhh, dst, out, t);
    }

    // ---- heads + packing (parallel over all T*N) ----
    head_kernel<<<8192, 256>>>(out, w_actor, b_actor, w_critic, b_critic,
                               actions, active, p0, pp0);
}